// round 15
// baseline (speedup 1.0000x reference)
#include <cuda_runtime.h>
#include <cuda_bf16.h>
#include <math_constants.h>
#include <cstdint>

// VQ forward: z (B,256) f32, embed (512,256) f32.
// out = [ quantized (B*256) | codes (B, as float) | commit (1) ]  (float32)
//
// Numerics contract (validated R9): exact dist = (zsq - 2*fmaf-chain-dot) + esq,
// argmin strict <, ascending, tie -> lower index. R14 computes the SAME argmin
// via: TF32 tensor-core approx scoring -> candidate set with rigorous margin ->
// exact fp32 chain re-ranking of candidates (or full row scan if flagged).

#define D_DIM 256
#define K_CODES 512
#define B_MAX 262144
#define MARGIN 2.0f

__device__ float g_esq[K_CODES];
__device__ float g_zsq[B_MAX];
__device__ float g_partials[B_MAX / 8];
__device__ short g_cand[B_MAX * 8];
__device__ unsigned char g_flag[B_MAX];

__device__ __forceinline__ uint32_t tf32r(float x) {
    uint32_t r;
    asm("cvt.rna.tf32.f32 %0, %1;" : "=r"(r) : "f"(x));
    return r;
}
__device__ __forceinline__ void mma_tf32(float* d,
    uint32_t a0, uint32_t a1, uint32_t a2, uint32_t a3,
    uint32_t b0, uint32_t b1) {
    asm volatile(
        "mma.sync.aligned.m16n8k8.row.col.f32.tf32.tf32.f32 "
        "{%0,%1,%2,%3}, {%4,%5,%6,%7}, {%8,%9}, {%0,%1,%2,%3};"
        : "+f"(d[0]), "+f"(d[1]), "+f"(d[2]), "+f"(d[3])
        : "r"(a0), "r"(a1), "r"(a2), "r"(a3), "r"(b0), "r"(b1));
}

// XLA:GPU row-reduce replica for sum(x*x) over a 256-float row.
// dest==0 -> g_esq, dest==1 -> g_zsq
__global__ void k_rowsq_xla(const float* __restrict__ x, int rows, int dest) {
    __shared__ float w[8];
    const unsigned full = 0xffffffffu;
    int grp = threadIdx.x >> 7;
    int t = threadIdx.x & 127;
    long row = (long)blockIdx.x * 2 + grp;

    float s = 0.f;
    if (row < rows) {
        const float2 v = *(const float2*)(x + row * D_DIM + 2 * t);
        s = __fadd_rn(__fmul_rn(v.x, v.x), __fmul_rn(v.y, v.y));
    }
    s = __fadd_rn(s, __shfl_down_sync(full, s, 16));
    s = __fadd_rn(s, __shfl_down_sync(full, s, 8));
    s = __fadd_rn(s, __shfl_down_sync(full, s, 4));
    s = __fadd_rn(s, __shfl_down_sync(full, s, 2));
    s = __fadd_rn(s, __shfl_down_sync(full, s, 1));
    if ((threadIdx.x & 31) == 0) w[threadIdx.x >> 5] = s;
    __syncthreads();
    if ((t >> 5) == 0) {
        int lane = t & 31;
        float v = (lane < 4) ? w[grp * 4 + lane] : 0.f;
        v = __fadd_rn(v, __shfl_down_sync(full, v, 16));
        v = __fadd_rn(v, __shfl_down_sync(full, v, 8));
        v = __fadd_rn(v, __shfl_down_sync(full, v, 4));
        v = __fadd_rn(v, __shfl_down_sync(full, v, 2));
        v = __fadd_rn(v, __shfl_down_sync(full, v, 1));
        if (lane == 0 && row < rows) {
            if (dest == 0) g_esq[row] = v;
            else           g_zsq[row] = v;
        }
    }
}

__device__ __forceinline__ void top2upd(float& m1, int& i1, float& m2,
                                        float s, int c) {
    if (s < m1) { m2 = m1; m1 = s; i1 = c; }
    else if (s < m2) { m2 = s; }
}

// Phase 1: TF32 MMA approx scoring + candidate selection.
// Block: 256 thr = 8 warps; 64 rows/block; warp = rowgroup(4) x colgroup(2).
// Per pass (2 passes of 256 cols): warp covers 16 rows x 128 cols.
__global__ __launch_bounds__(256)
void k_score(const float* __restrict__ z, const float* __restrict__ embed,
             int B) {
    __shared__ uint32_t Zt[32][72];     // [k][row] tf32, padded
    __shared__ uint32_t Et[32][264];    // [k][col] tf32, padded
    __shared__ float sM1[64][8];
    __shared__ float sM2[64][8];
    __shared__ short sI1[64][8];

    const int tid = threadIdx.x;
    const int w = tid >> 5, lane = tid & 31;
    const int rg = w >> 1, cg = w & 1;
    const int g = lane >> 2, q = lane & 3;
    const long rowBase = (long)blockIdx.x * 64;

    float m1a = CUDART_INF_F, m2a = CUDART_INF_F;
    float m1b = CUDART_INF_F, m2b = CUDART_INF_F;
    int i1a = 0, i1b = 0;

    const int zr = tid & 63, zk8 = tid >> 6;   // Z staging coords

    for (int pass = 0; pass < 2; pass++) {
        float acc[16][4];
#pragma unroll
        for (int t = 0; t < 16; t++)
#pragma unroll
            for (int j = 0; j < 4; j++) acc[t][j] = 0.f;

        for (int kt = 0; kt < 8; kt++) {
            __syncthreads();
            // stage Z tile 64x32 (tf32)
            {
                const float4* p = (const float4*)(z + (rowBase + zr) * D_DIM +
                                                  kt * 32 + zk8 * 8);
                float4 v0 = p[0], v1 = p[1];
                Zt[zk8 * 8 + 0][zr] = tf32r(v0.x);
                Zt[zk8 * 8 + 1][zr] = tf32r(v0.y);
                Zt[zk8 * 8 + 2][zr] = tf32r(v0.z);
                Zt[zk8 * 8 + 3][zr] = tf32r(v0.w);
                Zt[zk8 * 8 + 4][zr] = tf32r(v1.x);
                Zt[zk8 * 8 + 5][zr] = tf32r(v1.y);
                Zt[zk8 * 8 + 6][zr] = tf32r(v1.z);
                Zt[zk8 * 8 + 7][zr] = tf32r(v1.w);
            }
            // stage E tile 256x32 (tf32); col = tid
            {
                const float4* p = (const float4*)(embed +
                    (long)(pass * 256 + tid) * D_DIM + kt * 32);
#pragma unroll
                for (int j = 0; j < 8; j++) {
                    float4 v = p[j];
                    Et[j * 4 + 0][tid] = tf32r(v.x);
                    Et[j * 4 + 1][tid] = tf32r(v.y);
                    Et[j * 4 + 2][tid] = tf32r(v.z);
                    Et[j * 4 + 3][tid] = tf32r(v.w);
                }
            }
            __syncthreads();

#pragma unroll
            for (int k8 = 0; k8 < 4; k8++) {
                int k0 = k8 * 8;
                uint32_t a0 = Zt[k0 + q][rg * 16 + g];
                uint32_t a1 = Zt[k0 + q][rg * 16 + g + 8];
                uint32_t a2 = Zt[k0 + q + 4][rg * 16 + g];
                uint32_t a3 = Zt[k0 + q + 4][rg * 16 + g + 8];
#pragma unroll
                for (int t = 0; t < 16; t++) {
                    int c = cg * 128 + t * 8;
                    uint32_t b0 = Et[k0 + q][c + g];
                    uint32_t b1 = Et[k0 + q + 4][c + g];
                    mma_tf32(acc[t], a0, a1, a2, a3, b0, b1);
                }
            }
        }

        // finalize pass: approx score = esq - 2*dot; update per-row top2
#pragma unroll
        for (int t = 0; t < 16; t++) {
            int c0 = pass * 256 + cg * 128 + t * 8 + 2 * q;
            int c1 = c0 + 1;
            float e0 = g_esq[c0], e1 = g_esq[c1];
            float sa0 = e0 - 2.f * acc[t][0];
            float sa1 = e1 - 2.f * acc[t][1];
            float sb0 = e0 - 2.f * acc[t][2];
            float sb1 = e1 - 2.f * acc[t][3];
            top2upd(m1a, i1a, m2a, sa0, c0);
            top2upd(m1a, i1a, m2a, sa1, c1);
            top2upd(m1b, i1b, m2b, sb0, c0);
            top2upd(m1b, i1b, m2b, sb1, c1);
        }
    }

    // write per-thread slots
    __syncthreads();
    int slot = cg * 4 + q;
    sM1[rg * 16 + g][slot] = m1a;
    sM2[rg * 16 + g][slot] = m2a;
    sI1[rg * 16 + g][slot] = (short)i1a;
    sM1[rg * 16 + g + 8][slot] = m1b;
    sM2[rg * 16 + g + 8][slot] = m2b;
    sI1[rg * 16 + g + 8][slot] = (short)i1b;
    __syncthreads();

    if (tid < 64) {
        float rowmin = CUDART_INF_F;
#pragma unroll
        for (int s = 0; s < 8; s++)
            rowmin = fminf(rowmin, sM1[tid][s]);
        float thr = rowmin + MARGIN;
        int flag = 0;
        short cands[8];
        int nc = 0;
#pragma unroll
        for (int s = 0; s < 8; s++) {
            if (sM2[tid][s] <= thr) flag = 1;
            if (sM1[tid][s] <= thr) cands[nc++] = sI1[tid][s];
        }
        for (; nc < 8; nc++) cands[nc] = -1;
        g_flag[rowBase + tid] = (unsigned char)flag;
        int4 pk;
        pk.x = (int)(unsigned short)cands[0] | ((int)(unsigned short)cands[1] << 16);
        pk.y = (int)(unsigned short)cands[2] | ((int)(unsigned short)cands[3] << 16);
        pk.z = (int)(unsigned short)cands[4] | ((int)(unsigned short)cands[5] << 16);
        pk.w = (int)(unsigned short)cands[6] | ((int)(unsigned short)cands[7] << 16);
        *(int4*)&g_cand[(rowBase + tid) * 8] = pk;
    }
}

// Phase 2: exact re-rank (validated fp32 chain) + fused epilogue.
// Block 256 thr = 8 warps, warp per row.
__global__ __launch_bounds__(256)
void k_exact(const float* __restrict__ z, const float* __restrict__ embed,
             float* __restrict__ out, int B, int write_codes) {
    __shared__ float zrow[8][260];
    __shared__ float sWsum[8];
    const unsigned full = 0xffffffffu;
    const int w = threadIdx.x >> 5, lane = threadIdx.x & 31;
    const long row = (long)blockIdx.x * 8 + w;

    // stage z row
    const float4* zp = (const float4*)(z + row * D_DIM);
    float4 zv0 = zp[lane], zv1 = zp[lane + 32];
    *(float4*)&zrow[w][lane * 4] = zv0;
    *(float4*)&zrow[w][(lane + 32) * 4] = zv1;
    __syncwarp();

    float zsq = g_zsq[row];
    int flag = g_flag[row];
    float best = CUDART_INF_F;
    int bidx = 0x7fffffff;

    if (flag) {
        // full exact scan: 16 cols per lane, ascending
        for (int c = lane * 16; c < lane * 16 + 16; c++) {
            const float* e = embed + (long)c * D_DIM;
            float acc = 0.f;
#pragma unroll 8
            for (int k = 0; k < D_DIM; k++)
                acc = __fmaf_rn(zrow[w][k], __ldg(e + k), acc);
            float s = __fadd_rn(__fsub_rn(zsq, __fmul_rn(2.0f, acc)), g_esq[c]);
            if (s < best) { best = s; bidx = c; }
        }
    } else if (lane < 8) {
        short c = g_cand[row * 8 + lane];
        if (c >= 0) {
            const float* e = embed + (long)c * D_DIM;
            float acc = 0.f;
#pragma unroll 8
            for (int k = 0; k < D_DIM; k++)
                acc = __fmaf_rn(zrow[w][k], __ldg(e + k), acc);
            best = __fadd_rn(__fsub_rn(zsq, __fmul_rn(2.0f, acc)), g_esq[c]);
            bidx = c;
        }
    }

    // warp argmin reduce, tie -> lower index
#pragma unroll
    for (int off = 16; off > 0; off >>= 1) {
        float ov = __shfl_down_sync(full, best, off);
        int oi = __shfl_down_sync(full, bidx, off);
        if (ov < best || (ov == best && oi < bidx)) { best = ov; bidx = oi; }
    }
    int code = __shfl_sync(full, bidx, 0);

    if (lane == 0 && write_codes)
        out[(long)B * D_DIM + row] = (float)code;

    // epilogue: quantized = z + (q - z), commit partial
    const float4* ep = (const float4*)(embed + (long)code * D_DIM);
    float4* o4 = (float4*)out;
    float lsum = 0.f;
#pragma unroll
    for (int h = 0; h < 2; h++) {
        int i = lane + 32 * h;
        float4 qv = __ldg(ep + i);
        float4 zv = *(const float4*)&zrow[w][i * 4];
        float dx = __fsub_rn(qv.x, zv.x);
        float dy = __fsub_rn(qv.y, zv.y);
        float dz = __fsub_rn(qv.z, zv.z);
        float dw = __fsub_rn(qv.w, zv.w);
        float4 ov;
        ov.x = __fadd_rn(zv.x, dx);
        ov.y = __fadd_rn(zv.y, dy);
        ov.z = __fadd_rn(zv.z, dz);
        ov.w = __fadd_rn(zv.w, dw);
        o4[row * 64 + i] = ov;
        lsum += dx * dx + dy * dy + dz * dz + dw * dw;
    }
#pragma unroll
    for (int off = 16; off > 0; off >>= 1)
        lsum += __shfl_down_sync(full, lsum, off);
    if (lane == 0) sWsum[w] = lsum;
    __syncthreads();
    if (threadIdx.x == 0) {
        float s = 0.f;
#pragma unroll
        for (int i = 0; i < 8; i++) s += sWsum[i];
        g_partials[blockIdx.x] = s;
    }
}

__global__ void k_fin(float* __restrict__ out, int nblk, long BD, long B) {
    __shared__ double sp[256];
    int tid = threadIdx.x;
    double s = 0.0;
    for (int i = tid; i < nblk; i += 256) s += (double)g_partials[i];
    sp[tid] = s;
    __syncthreads();
    for (int st = 128; st > 0; st >>= 1) {
        if (tid < st) sp[tid] += sp[tid + st];
        __syncthreads();
    }
    if (tid == 0) {
        double commit = 0.25 * sp[0] / (double)BD;
        out[BD + B] = (float)commit;
    }
}

extern "C" void kernel_launch(void* const* d_in, const int* in_sizes, int n_in,
                              void* d_out, int out_size) {
    const float* z = (const float*)d_in[0];
    const float* embed = (const float*)d_in[1];
    float* out = (float*)d_out;

    int B = in_sizes[0] / D_DIM;
    long BD = (long)B * D_DIM;
    int write_codes = ((long)out_size >= BD + B) ? 1 : 0;
    int write_commit = ((long)out_size >= BD + B + 1) ? 1 : 0;

    k_rowsq_xla<<<(K_CODES + 1) / 2, 256>>>(embed, K_CODES, /*dest=*/0);
    k_rowsq_xla<<<(B + 1) / 2, 256>>>(z, B, /*dest=*/1);
    k_score<<<B / 64, 256>>>(z, embed, B);
    k_exact<<<B / 8, 256>>>(z, embed, out, B, write_codes);
    if (write_commit)
        k_fin<<<1, 256>>>(out, B / 8, BD, (long)B);
}

// round 17
// speedup vs baseline: 1.7800x; 1.7800x over previous
#include <cuda_runtime.h>
#include <cuda_bf16.h>
#include <math_constants.h>

// VQ forward: z (B,256) f32, embed (512,256) f32.
// out = [ quantized (B*256) | codes (B, as float) | commit (1) ]  (float32)
//
// Numerics contract (validated R9, PASS):
//   dot:    single-accumulator fp32 fma chain, k ascending (per row,col)
//   z_sq/e_sq: XLA:GPU row-reduce (vec=2, 128 thr, shfl trees)
//   dist = (z_sq - (2.0f*dot)) + e_sq  (separately rounded)
//   argmin: strict <, ascending col, tie -> lower index
//   quantized = z + (q - z), separately rounded
//
// R16 = R9 structure exactly, but the Z tile is stored DUPLICATED as float2
// (z,z) so a-operands need no pack movs, and b-operands come as register-pair
// views of the plain E tile (ulonglong2 load). Inner k-step: 3x LDS.128 +
// 8x FFMA2 = 11 issue slots / 16 FMA (R9: 16/16). Crossbar: 4 phases/warp/k
// (a-loads broadcast, b spans 256B) vs R12's fatal 9.

#define D_DIM 256
#define K_CODES 512
#define TM 64
#define TN 64
#define TK 16
#define NTHREADS 256
#define B_MAX 262144

__device__ float g_esq[K_CODES];
__device__ float g_zsq[B_MAX];
__device__ float g_partials[8192];

__device__ __forceinline__ void fma2(unsigned long long& d,
                                     unsigned long long a,
                                     unsigned long long b) {
    asm("fma.rn.f32x2 %0, %1, %2, %0;" : "+l"(d) : "l"(a), "l"(b));
}
__device__ __forceinline__ float2 upk2(unsigned long long v) {
    float2 f;
    asm("mov.b64 {%0, %1}, %2;" : "=f"(f.x), "=f"(f.y) : "l"(v));
    return f;
}

// XLA:GPU row-reduce replica for sum(x*x) over a 256-float row.
// dest==0 -> g_esq, dest==1 -> g_zsq (symbols touched in device code only)
__global__ void k_rowsq_xla(const float* __restrict__ x, int rows, int dest) {
    __shared__ float w[8];
    const unsigned full = 0xffffffffu;
    int grp = threadIdx.x >> 7;
    int t = threadIdx.x & 127;
    long row = (long)blockIdx.x * 2 + grp;

    float s = 0.f;
    if (row < rows) {
        const float2 v = *(const float2*)(x + row * D_DIM + 2 * t);
        s = __fadd_rn(__fmul_rn(v.x, v.x), __fmul_rn(v.y, v.y));
    }
    s = __fadd_rn(s, __shfl_down_sync(full, s, 16));
    s = __fadd_rn(s, __shfl_down_sync(full, s, 8));
    s = __fadd_rn(s, __shfl_down_sync(full, s, 4));
    s = __fadd_rn(s, __shfl_down_sync(full, s, 2));
    s = __fadd_rn(s, __shfl_down_sync(full, s, 1));
    if ((threadIdx.x & 31) == 0) w[threadIdx.x >> 5] = s;
    __syncthreads();
    if ((t >> 5) == 0) {
        int lane = t & 31;
        float v = (lane < 4) ? w[grp * 4 + lane] : 0.f;
        v = __fadd_rn(v, __shfl_down_sync(full, v, 16));
        v = __fadd_rn(v, __shfl_down_sync(full, v, 8));
        v = __fadd_rn(v, __shfl_down_sync(full, v, 4));
        v = __fadd_rn(v, __shfl_down_sync(full, v, 2));
        v = __fadd_rn(v, __shfl_down_sync(full, v, 1));
        if (lane == 0 && row < rows) {
            if (dest == 0) g_esq[row] = v;
            else           g_zsq[row] = v;
        }
    }
}

__global__ __launch_bounds__(NTHREADS)
void k_main(const float* __restrict__ z, const float* __restrict__ embed,
            float* __restrict__ out, int B, int write_codes) {
    __shared__ __align__(16) float2 Zd[TK][TM + 2];  // duplicated Z, padded row
    __shared__ __align__(16) float  Es[TK][TN];      // plain E tile
    __shared__ float sMin[TM][16];
    __shared__ int   sIdx[TM][16];
    __shared__ int   sCode[TM];
    __shared__ float sPart[NTHREADS];
    __shared__ float sZsq[TM];

    const int tid = threadIdx.x;
    const int tx = tid & 15;          // cols tx*4 .. tx*4+3
    const int ty = tid >> 4;          // rows ty*4 .. ty*4+3
    const long rowBase = (long)blockIdx.x * TM;

    if (tid < TM) sZsq[tid] = g_zsq[rowBase + tid];

    float rmin[4];
    int   ridx[4];
#pragma unroll
    for (int r = 0; r < 4; r++) { rmin[r] = CUDART_INF_F; ridx[r] = 0; }

    const int mLd = tid >> 2;         // 0..63 : row/code index for tile loads
    const int kq  = tid & 3;          // 0..3  : which float4 along k

    for (int ct = 0; ct < K_CODES / TN; ++ct) {
        unsigned long long acc[4][2];   // [row][colpair]
#pragma unroll
        for (int r = 0; r < 4; r++) { acc[r][0] = 0ull; acc[r][1] = 0ull; }

        for (int kt = 0; kt < D_DIM / TK; ++kt) {
            // ---- stage tiles (transposed into [k][m]) ----
            float4 zv = *(const float4*)(z + (rowBase + mLd) * D_DIM + kt * TK + kq * 4);
            Zd[kq * 4 + 0][mLd] = make_float2(zv.x, zv.x);
            Zd[kq * 4 + 1][mLd] = make_float2(zv.y, zv.y);
            Zd[kq * 4 + 2][mLd] = make_float2(zv.z, zv.z);
            Zd[kq * 4 + 3][mLd] = make_float2(zv.w, zv.w);
            float4 ev = *(const float4*)(embed + (long)(ct * TN + mLd) * D_DIM + kt * TK + kq * 4);
            Es[kq * 4 + 0][mLd] = ev.x;
            Es[kq * 4 + 1][mLd] = ev.y;
            Es[kq * 4 + 2][mLd] = ev.z;
            Es[kq * 4 + 3][mLd] = ev.w;
            __syncthreads();

            // ---- 16 k-steps: 2x LDS.128 (a dup pairs) + 1x LDS.128 (b)
            //      + 8 FFMA2 = 11 issue slots, zero movs ----
#pragma unroll
            for (int k = 0; k < TK; k++) {
                ulonglong2 a01 = *(const ulonglong2*)&Zd[k][ty * 4];
                ulonglong2 a23 = *(const ulonglong2*)&Zd[k][ty * 4 + 2];
                ulonglong2 b   = *(const ulonglong2*)&Es[k][tx * 4];
                fma2(acc[0][0], a01.x, b.x); fma2(acc[0][1], a01.x, b.y);
                fma2(acc[1][0], a01.y, b.x); fma2(acc[1][1], a01.y, b.y);
                fma2(acc[2][0], a23.x, b.x); fma2(acc[2][1], a23.x, b.y);
                fma2(acc[3][0], a23.y, b.x); fma2(acc[3][1], a23.y, b.y);
            }
            __syncthreads();
        }

        // ---- dist = (z_sq - (2*dot)) + e_sq; running argmin, cols asc ----
        int cb = ct * TN + tx * 4;
        float e0 = g_esq[cb + 0];
        float e1 = g_esq[cb + 1];
        float e2 = g_esq[cb + 2];
        float e3 = g_esq[cb + 3];
#pragma unroll
        for (int r = 0; r < 4; r++) {
            float zs = sZsq[ty * 4 + r];
            float2 d01 = upk2(acc[r][0]);
            float2 d23 = upk2(acc[r][1]);
            float s0 = __fadd_rn(__fsub_rn(zs, __fmul_rn(2.0f, d01.x)), e0);
            float s1 = __fadd_rn(__fsub_rn(zs, __fmul_rn(2.0f, d01.y)), e1);
            float s2 = __fadd_rn(__fsub_rn(zs, __fmul_rn(2.0f, d23.x)), e2);
            float s3 = __fadd_rn(__fsub_rn(zs, __fmul_rn(2.0f, d23.y)), e3);
            if (s0 < rmin[r]) { rmin[r] = s0; ridx[r] = cb + 0; }
            if (s1 < rmin[r]) { rmin[r] = s1; ridx[r] = cb + 1; }
            if (s2 < rmin[r]) { rmin[r] = s2; ridx[r] = cb + 2; }
            if (s3 < rmin[r]) { rmin[r] = s3; ridx[r] = cb + 3; }
        }
    }

    // ---- cross-thread argmin reduce (lower index wins ties) ----
#pragma unroll
    for (int r = 0; r < 4; r++) {
        sMin[ty * 4 + r][tx] = rmin[r];
        sIdx[ty * 4 + r][tx] = ridx[r];
    }
    __syncthreads();
    if (tid < TM) {
        float m = sMin[tid][0];
        int ix = sIdx[tid][0];
#pragma unroll
        for (int x = 1; x < 16; x++) {
            float v = sMin[tid][x];
            int i2 = sIdx[tid][x];
            if (v < m || (v == m && i2 < ix)) { m = v; ix = i2; }
        }
        sCode[tid] = ix;
        if (write_codes)
            out[(long)B * D_DIM + rowBase + tid] = (float)ix;
    }
    __syncthreads();

    // ---- epilogue: gather q, quantized = z + (q - z), commit partial ----
    float lsum = 0.f;
    const float4* z4 = (const float4*)z;
    const float4* e4 = (const float4*)embed;
    float4* o4 = (float4*)out;
#pragma unroll 4
    for (int i = tid; i < TM * (D_DIM / 4); i += NTHREADS) {
        int r = i >> 6;
        int c = i & 63;
        int code = sCode[r];
        float4 qv = __ldg(&e4[(long)code * (D_DIM / 4) + c]);
        float4 zv = z4[(rowBase + r) * (D_DIM / 4) + c];
        float dx = __fsub_rn(qv.x, zv.x);
        float dy = __fsub_rn(qv.y, zv.y);
        float dz = __fsub_rn(qv.z, zv.z);
        float dw = __fsub_rn(qv.w, zv.w);
        float4 ov;
        ov.x = __fadd_rn(zv.x, dx);
        ov.y = __fadd_rn(zv.y, dy);
        ov.z = __fadd_rn(zv.z, dz);
        ov.w = __fadd_rn(zv.w, dw);
        o4[(rowBase + r) * (D_DIM / 4) + c] = ov;
        lsum += dx * dx + dy * dy + dz * dz + dw * dw;
    }
    sPart[tid] = lsum;
    __syncthreads();
#pragma unroll
    for (int s = NTHREADS / 2; s > 0; s >>= 1) {
        if (tid < s) sPart[tid] += sPart[tid + s];
        __syncthreads();
    }
    if (tid == 0) g_partials[blockIdx.x] = sPart[0];
}

__global__ void k_fin(float* __restrict__ out, int nblk, long BD, long B) {
    __shared__ double sp[256];
    int tid = threadIdx.x;
    double s = 0.0;
    for (int i = tid; i < nblk; i += 256) s += (double)g_partials[i];
    sp[tid] = s;
    __syncthreads();
    for (int st = 128; st > 0; st >>= 1) {
        if (tid < st) sp[tid] += sp[tid + st];
        __syncthreads();
    }
    if (tid == 0) {
        double commit = 0.25 * sp[0] / (double)BD;
        out[BD + B] = (float)commit;
    }
}

extern "C" void kernel_launch(void* const* d_in, const int* in_sizes, int n_in,
                              void* d_out, int out_size) {
    const float* z = (const float*)d_in[0];
    const float* embed = (const float*)d_in[1];
    float* out = (float*)d_out;

    int B = in_sizes[0] / D_DIM;
    long BD = (long)B * D_DIM;
    int nblk = B / TM;
    int write_codes = ((long)out_size >= BD + B) ? 1 : 0;
    int write_commit = ((long)out_size >= BD + B + 1) ? 1 : 0;

    k_rowsq_xla<<<(K_CODES + 1) / 2, 256>>>(embed, K_CODES, /*dest=*/0);
    k_rowsq_xla<<<(B + 1) / 2, 256>>>(z, B, /*dest=*/1);
    k_main<<<nblk, NTHREADS>>>(z, embed, out, B, write_codes);
    if (write_commit)
        k_fin<<<1, 256>>>(out, nblk, BD, (long)B);
}